// round 1
// baseline (speedup 1.0000x reference)
#include <cuda_runtime.h>
#include <math.h>

#define NN   50000
#define NE   800000
#define TOTE (NE + NN)
#define HC   128
#define NH   4
#define EMBD 64

// ---- scratch (device globals; no allocation allowed) ----
__device__ float  g_x[NN * HC];
__device__ float  g_h[NN * HC];
__device__ float  g_als[NN * NH];
__device__ float  g_ald[NN * NH];
__device__ int    g_srcs[TOTE];
__device__ int    g_rowptr[NN + 1];
__device__ int    g_cursor[NN];
__device__ int    g_deg[NN];
__device__ double g_sum;
__device__ double g_sumsq;

// ---------------------------------------------------------------------------
__global__ void k_init() {
    int i = blockIdx.x * blockDim.x + threadIdx.x;
    if (i < NN) g_deg[i] = 1;           // self-loop pre-counted
    if (i == 0) { g_sum = 0.0; g_sumsq = 0.0; }
}

__global__ void k_rq(const float* __restrict__ rq) {
    __shared__ double ss[256], ss2[256];
    double s = 0.0, s2 = 0.0;
    for (int i = blockIdx.x * blockDim.x + threadIdx.x; i < NN;
         i += gridDim.x * blockDim.x) {
        double v = (double)rq[i];
        s += v; s2 += v * v;
    }
    ss[threadIdx.x] = s; ss2[threadIdx.x] = s2;
    __syncthreads();
    for (int o = 128; o; o >>= 1) {
        if (threadIdx.x < o) {
            ss[threadIdx.x]  += ss[threadIdx.x + o];
            ss2[threadIdx.x] += ss2[threadIdx.x + o];
        }
        __syncthreads();
    }
    if (threadIdx.x == 0) {
        atomicAdd(&g_sum,  ss[0]);
        atomicAdd(&g_sumsq, ss2[0]);
    }
}

__global__ void k_hist(const int* __restrict__ ei) {
    int e = blockIdx.x * blockDim.x + threadIdx.x;
    if (e < NE) atomicAdd(&g_deg[ei[NE + e]], 1);
}

// single-block exclusive scan over g_deg -> g_rowptr / g_cursor
__global__ void k_scan() {
    __shared__ int sd[1024];
    int t = threadIdx.x;
    int carry = 0;
    for (int base = 0; base < NN; base += 1024) {
        int v = (base + t < NN) ? g_deg[base + t] : 0;
        sd[t] = v;
        __syncthreads();
        for (int off = 1; off < 1024; off <<= 1) {
            int x = (t >= off) ? sd[t - off] : 0;
            __syncthreads();
            sd[t] += x;
            __syncthreads();
        }
        if (base + t < NN) {
            int ex = carry + sd[t] - v;
            g_rowptr[base + t] = ex;
            g_cursor[base + t] = ex;
        }
        int tot = sd[1023];
        __syncthreads();
        carry += tot;
    }
    if (t == 0) g_rowptr[NN] = carry;
}

__global__ void k_scatter(const int* __restrict__ ei) {
    int e = blockIdx.x * blockDim.x + threadIdx.x;
    if (e >= TOTE) return;
    int s, d;
    if (e < NE) { s = ei[e]; d = ei[NE + e]; }
    else        { s = e - NE; d = s; }
    int pos = atomicAdd(&g_cursor[d], 1);
    g_srcs[pos] = s;
}

__global__ void k_x0(const int* __restrict__ label, const float* __restrict__ rq,
                     const float* __restrict__ emb, const float* __restrict__ rw,
                     const float* __restrict__ rb) {
    int idx = blockIdx.x * blockDim.x + threadIdx.x;
    if (idx >= NN * EMBD) return;
    int i = idx >> 6, j = idx & 63;
    double mean = g_sum / NN;
    double var  = (g_sumsq - NN * mean * mean) / (NN - 1);
    float  stdv = (float)sqrt(var);
    float  rqn  = (rq[i] - (float)mean) / (stdv + 1e-6f);
    g_x[i * HC + j]        = emb[label[i] * EMBD + j];
    g_x[i * HC + EMBD + j] = rqn * rw[j] + rb[j];
}

// ---------------------------------------------------------------------------
// GEMM: O[n,128] = X[n,128] @ W[128,128], fp32. 64-row tile, K-tile 32.
__global__ __launch_bounds__(256) void k_gemm(const float* __restrict__ X,
                                              const float* __restrict__ W,
                                              float* __restrict__ O) {
    __shared__ float xs[64][33];
    __shared__ float ws[32][HC];
    int tid = threadIdx.x;
    int ty  = tid >> 5, tx = tid & 31;
    int row0 = blockIdx.x * 64;

    float acc[8][4];
#pragma unroll
    for (int r = 0; r < 8; r++)
#pragma unroll
        for (int j = 0; j < 4; j++) acc[r][j] = 0.0f;

    for (int kb = 0; kb < HC; kb += 32) {
#pragma unroll
        for (int j = 0; j < 8; j++) {       // 64x32 x-tile
            int idx = j * 256 + tid;
            int row = idx >> 5, k = idx & 31;
            float v = 0.0f;
            if (row0 + row < NN) v = X[(row0 + row) * HC + kb + k];
            xs[row][k] = v;
        }
#pragma unroll
        for (int j = 0; j < 16; j++) {      // 32x128 w-tile
            int idx = j * 256 + tid;
            int k = idx >> 7, c = idx & 127;
            ws[k][c] = W[(kb + k) * HC + c];
        }
        __syncthreads();
#pragma unroll
        for (int k = 0; k < 32; k++) {
            float4 b4 = *(const float4*)&ws[k][tx * 4];
#pragma unroll
            for (int r = 0; r < 8; r++) {
                float a = xs[ty * 8 + r][k];
                acc[r][0] += a * b4.x;
                acc[r][1] += a * b4.y;
                acc[r][2] += a * b4.z;
                acc[r][3] += a * b4.w;
            }
        }
        __syncthreads();
    }
#pragma unroll
    for (int r = 0; r < 8; r++) {
        int row = row0 + ty * 8 + r;
        if (row < NN) {
            float4 v = make_float4(acc[r][0], acc[r][1], acc[r][2], acc[r][3]);
            ((float4*)O)[row * 32 + tx] = v;
        }
    }
}

// attention logit sums: al_s[i,h] = sum_c h[i,h,c]*a_src[h,c]; likewise al_d.
__global__ void k_al(const float* __restrict__ asrc, const float* __restrict__ adst) {
    int node = blockIdx.x * (blockDim.x >> 5) + (threadIdx.x >> 5);
    int lane = threadIdx.x & 31;
    if (node >= NN) return;
    float4 h4  = ((const float4*)g_h)[node * 32 + lane];
    float4 as4 = ((const float4*)asrc)[lane];
    float4 ad4 = ((const float4*)adst)[lane];
    float s = h4.x * as4.x + h4.y * as4.y + h4.z * as4.z + h4.w * as4.w;
    float d = h4.x * ad4.x + h4.y * ad4.y + h4.z * ad4.z + h4.w * ad4.w;
#pragma unroll
    for (int off = 4; off; off >>= 1) {
        s += __shfl_down_sync(0xffffffffu, s, off);
        d += __shfl_down_sync(0xffffffffu, d, off);
    }
    if ((lane & 7) == 0) {
        int head = lane >> 3;
        g_als[node * NH + head] = s;
        g_ald[node * NH + head] = d;
    }
}

__device__ __forceinline__ float gelu_exact(float x) {
    return 0.5f * x * (1.0f + erff(x * 0.70710678118654752f));
}

// one warp per destination node: softmax over its edge segment + weighted sum
__global__ void k_agg(const float* __restrict__ bias, float* __restrict__ out) {
    int dst  = blockIdx.x * (blockDim.x >> 5) + (threadIdx.x >> 5);
    int lane = threadIdx.x & 31;
    if (dst >= NN) return;
    int beg = g_rowptr[dst], end = g_rowptr[dst + 1];
    int head = lane >> 3;
    float ald = g_ald[dst * NH + head];

    float m = -1e30f;
    for (int e = beg; e < end; e++) {
        int s = g_srcs[e];
        float v = g_als[s * NH + head] + ald;
        v = v > 0.0f ? v : 0.2f * v;
        m = fmaxf(m, v);
    }
    float  ssum = 0.0f;
    float4 acc  = make_float4(0.f, 0.f, 0.f, 0.f);
    for (int e = beg; e < end; e++) {
        int s = g_srcs[e];
        float v = g_als[s * NH + head] + ald;
        v = v > 0.0f ? v : 0.2f * v;
        float p = __expf(v - m);
        ssum += p;
        float4 h4 = ((const float4*)g_h)[s * 32 + lane];
        acc.x += p * h4.x;
        acc.y += p * h4.y;
        acc.z += p * h4.z;
        acc.w += p * h4.w;
    }
    float  inv = 1.0f / (ssum + 1e-16f);
    float4 b4  = ((const float4*)bias)[lane];
    float4 r;
    r.x = gelu_exact(acc.x * inv + b4.x);
    r.y = gelu_exact(acc.y * inv + b4.y);
    r.z = gelu_exact(acc.z * inv + b4.z);
    r.w = gelu_exact(acc.w * inv + b4.w);
    ((float4*)out)[dst * 32 + lane] = r;
}

// last-layer variant writes gelu'd output directly to d_out (same code, param).

extern "C" void kernel_launch(void* const* d_in, const int* in_sizes, int n_in,
                              void* d_out, int out_size) {
    const int*   label = (const int*)d_in[0];
    const int*   ei    = (const int*)d_in[1];
    // d_in[2] = weight (unused by GATConv)
    const float* rq    = (const float*)d_in[3];
    const float* emb   = (const float*)d_in[4];
    const float* rw    = (const float*)d_in[5];
    const float* rb    = (const float*)d_in[6];
    const float* W0    = (const float*)d_in[7];
    const float* as0   = (const float*)d_in[8];
    const float* ad0   = (const float*)d_in[9];
    const float* b0    = (const float*)d_in[10];
    const float* W1    = (const float*)d_in[11];
    const float* as1   = (const float*)d_in[12];
    const float* ad1   = (const float*)d_in[13];
    const float* b1    = (const float*)d_in[14];
    const float* W2    = (const float*)d_in[15];
    const float* as2   = (const float*)d_in[16];
    const float* ad2   = (const float*)d_in[17];
    const float* b2    = (const float*)d_in[18];
    float* out = (float*)d_out;

    float* g_x_p;   cudaGetSymbolAddress((void**)&g_x_p, g_x);
    float* g_h_p;   cudaGetSymbolAddress((void**)&g_h_p, g_h);

    // preprocessing
    k_init<<<(NN + 255) / 256, 256>>>();
    k_rq<<<256, 256>>>(rq);
    k_hist<<<(NE + 255) / 256, 256>>>(ei);
    k_scan<<<1, 1024>>>();
    k_scatter<<<(TOTE + 255) / 256, 256>>>(ei);
    k_x0<<<(NN * EMBD + 255) / 256, 256>>>(label, rq, emb, rw, rb);

    const int gemm_blocks = (NN + 63) / 64;
    const int warp_blocks = (NN + 7) / 8;   // 8 warps per 256-thread block

    // layer 0
    k_gemm<<<gemm_blocks, 256>>>(g_x_p, W0, g_h_p);
    k_al<<<warp_blocks, 256>>>(as0, ad0);
    k_agg<<<warp_blocks, 256>>>(b0, g_x_p);
    // layer 1
    k_gemm<<<gemm_blocks, 256>>>(g_x_p, W1, g_h_p);
    k_al<<<warp_blocks, 256>>>(as1, ad1);
    k_agg<<<warp_blocks, 256>>>(b1, g_x_p);
    // layer 2
    k_gemm<<<gemm_blocks, 256>>>(g_x_p, W2, g_h_p);
    k_al<<<warp_blocks, 256>>>(as2, ad2);
    k_agg<<<warp_blocks, 256>>>(b2, out);
}

// round 2
// speedup vs baseline: 1.1793x; 1.1793x over previous
#include <cuda_runtime.h>
#include <math.h>

#define NN   50000
#define NE   800000
#define TOTE (NE + NN)
#define HC   128
#define NH   4
#define EMBD 64
#define SCAN_B 1024
#define NBLK  ((NN + SCAN_B - 1) / SCAN_B)   // 49

// ---- scratch (device globals; no allocation allowed) ----
__device__ float  g_x[NN * HC];
__device__ float  g_h[NN * HC];
__device__ float  g_als[NN * NH];
__device__ float  g_ald[NN * NH];
__device__ int    g_srcs[TOTE];
__device__ int    g_rowptr[NN + 1];
__device__ int    g_cursor[NN];
__device__ int    g_deg[NN];
__device__ int    g_bsum[NBLK];
__device__ int    g_boff[NBLK];
__device__ double g_sum;
__device__ double g_sumsq;

// ---------------------------------------------------------------------------
__global__ void k_init() {
    int i = blockIdx.x * blockDim.x + threadIdx.x;
    if (i < NN) g_deg[i] = 1;           // self-loop pre-counted
    if (i == 0) { g_sum = 0.0; g_sumsq = 0.0; }
}

__global__ void k_rq(const float* __restrict__ rq) {
    __shared__ double ss[256], ss2[256];
    double s = 0.0, s2 = 0.0;
    for (int i = blockIdx.x * blockDim.x + threadIdx.x; i < NN;
         i += gridDim.x * blockDim.x) {
        double v = (double)rq[i];
        s += v; s2 += v * v;
    }
    ss[threadIdx.x] = s; ss2[threadIdx.x] = s2;
    __syncthreads();
    for (int o = 128; o; o >>= 1) {
        if (threadIdx.x < o) {
            ss[threadIdx.x]  += ss[threadIdx.x + o];
            ss2[threadIdx.x] += ss2[threadIdx.x + o];
        }
        __syncthreads();
    }
    if (threadIdx.x == 0) {
        atomicAdd(&g_sum,  ss[0]);
        atomicAdd(&g_sumsq, ss2[0]);
    }
}

__global__ void k_hist(const int* __restrict__ ei) {
    int e = blockIdx.x * blockDim.x + threadIdx.x;
    if (e < NE) atomicAdd(&g_deg[__ldg(ei + NE + e)], 1);
}

// ---- parallel 3-phase exclusive scan over g_deg ----
__global__ void k_scan1() {
    __shared__ int sd[SCAN_B];
    int t = threadIdx.x;
    int gi = blockIdx.x * SCAN_B + t;
    int v = (gi < NN) ? g_deg[gi] : 0;
    sd[t] = v;
    __syncthreads();
#pragma unroll
    for (int off = 1; off < SCAN_B; off <<= 1) {
        int x = (t >= off) ? sd[t - off] : 0;
        __syncthreads();
        sd[t] += x;
        __syncthreads();
    }
    if (gi < NN) g_rowptr[gi] = sd[t] - v;          // exclusive within block
    if (t == SCAN_B - 1) g_bsum[blockIdx.x] = sd[t];
}

__global__ void k_scan2() {                          // 1 block, 64 threads
    __shared__ int sd[64];
    int t = threadIdx.x;
    int v = (t < NBLK) ? g_bsum[t] : 0;
    sd[t] = v;
    __syncthreads();
#pragma unroll
    for (int off = 1; off < 64; off <<= 1) {
        int x = (t >= off) ? sd[t - off] : 0;
        __syncthreads();
        sd[t] += x;
        __syncthreads();
    }
    if (t < NBLK) g_boff[t] = sd[t] - v;             // exclusive
}

__global__ void k_scan3() {
    int i = blockIdx.x * blockDim.x + threadIdx.x;
    if (i < NN) {
        int r = g_rowptr[i] + g_boff[i / SCAN_B];
        g_rowptr[i] = r;
        g_cursor[i] = r;
    }
    if (i == 0) g_rowptr[NN] = TOTE;
}

__global__ void k_scatter(const int* __restrict__ ei) {
    int e = blockIdx.x * blockDim.x + threadIdx.x;
    if (e >= TOTE) return;
    int s, d;
    if (e < NE) { s = __ldg(ei + e); d = __ldg(ei + NE + e); }
    else        { s = e - NE; d = s; }
    int pos = atomicAdd(&g_cursor[d], 1);
    g_srcs[pos] = s;
}

__global__ void k_x0(const int* __restrict__ label, const float* __restrict__ rq,
                     const float* __restrict__ emb, const float* __restrict__ rw,
                     const float* __restrict__ rb) {
    int idx = blockIdx.x * blockDim.x + threadIdx.x;
    if (idx >= NN * EMBD) return;
    int i = idx >> 6, j = idx & 63;
    double mean = g_sum / NN;
    double var  = (g_sumsq - NN * mean * mean) / (NN - 1);
    float  stdv = (float)sqrt(var);
    float  rqn  = (rq[i] - (float)mean) / (stdv + 1e-6f);
    g_x[i * HC + j]        = emb[label[i] * EMBD + j];
    g_x[i * HC + EMBD + j] = rqn * rw[j] + rb[j];
}

// ---------------------------------------------------------------------------
// GEMM: O[n,128] = X[n,128] @ W[128,128], fp32, fused attention-logit epilogue.
// 64-row tile, K-tile 32, 8 warps (one per 8-row slab), thread = 8 rows x 4 cols.
__global__ __launch_bounds__(256) void k_gemm(const float* __restrict__ X,
                                              const float* __restrict__ W,
                                              float* __restrict__ O,
                                              const float* __restrict__ asrc,
                                              const float* __restrict__ adst) {
    __shared__ float xs[64][33];
    __shared__ float ws[32][HC];
    int tid = threadIdx.x;
    int ty  = tid >> 5, tx = tid & 31;
    int row0 = blockIdx.x * 64;

    float acc[8][4];
#pragma unroll
    for (int r = 0; r < 8; r++)
#pragma unroll
        for (int j = 0; j < 4; j++) acc[r][j] = 0.0f;

    for (int kb = 0; kb < HC; kb += 32) {
#pragma unroll
        for (int j = 0; j < 8; j++) {       // 64x32 x-tile
            int idx = j * 256 + tid;
            int row = idx >> 5, k = idx & 31;
            float v = 0.0f;
            if (row0 + row < NN) v = X[(row0 + row) * HC + kb + k];
            xs[row][k] = v;
        }
#pragma unroll
        for (int j = 0; j < 16; j++) {      // 32x128 w-tile
            int idx = j * 256 + tid;
            int k = idx >> 7, c = idx & 127;
            ws[k][c] = W[(kb + k) * HC + c];
        }
        __syncthreads();
#pragma unroll
        for (int k = 0; k < 32; k++) {
            float4 b4 = *(const float4*)&ws[k][tx * 4];
#pragma unroll
            for (int r = 0; r < 8; r++) {
                float a = xs[ty * 8 + r][k];
                acc[r][0] += a * b4.x;
                acc[r][1] += a * b4.y;
                acc[r][2] += a * b4.z;
                acc[r][3] += a * b4.w;
            }
        }
        __syncthreads();
    }

    float4 as4 = ((const float4*)asrc)[tx];
    float4 ad4 = ((const float4*)adst)[tx];
    int head = tx >> 3;
#pragma unroll
    for (int r = 0; r < 8; r++) {
        int row = row0 + ty * 8 + r;
        if (row < NN) {
            float4 v = make_float4(acc[r][0], acc[r][1], acc[r][2], acc[r][3]);
            ((float4*)O)[row * 32 + tx] = v;
            float s = v.x * as4.x + v.y * as4.y + v.z * as4.z + v.w * as4.w;
            float d = v.x * ad4.x + v.y * ad4.y + v.z * ad4.z + v.w * ad4.w;
#pragma unroll
            for (int off = 4; off; off >>= 1) {
                s += __shfl_down_sync(0xffffffffu, s, off, 8);
                d += __shfl_down_sync(0xffffffffu, d, off, 8);
            }
            if ((tx & 7) == 0) {
                g_als[row * NH + head] = s;
                g_ald[row * NH + head] = d;
            }
        }
    }
}

__device__ __forceinline__ float gelu_exact(float x) {
    return 0.5f * x * (1.0f + erff(x * 0.70710678118654752f));
}

// one warp per destination node: ONLINE softmax + weighted sum (single pass)
__global__ void k_agg(const float* __restrict__ bias, float* __restrict__ out) {
    int dst  = blockIdx.x * (blockDim.x >> 5) + (threadIdx.x >> 5);
    int lane = threadIdx.x & 31;
    if (dst >= NN) return;
    int beg = g_rowptr[dst], end = g_rowptr[dst + 1];
    int head = lane >> 3;
    float ald = g_ald[dst * NH + head];

    float  m    = -1e30f;
    float  ssum = 0.0f;
    float4 acc  = make_float4(0.f, 0.f, 0.f, 0.f);
    for (int e = beg; e < end; e++) {
        int s = __ldg(g_srcs + e);
        float v = __ldg(g_als + s * NH + head) + ald;
        v = v > 0.0f ? v : 0.2f * v;
        float mnew  = fmaxf(m, v);
        float scale = __expf(m - mnew);     // first iter: exp(-inf) = 0
        float p     = __expf(v - mnew);
        m = mnew;
        ssum = ssum * scale + p;
        float4 h4 = __ldg((const float4*)g_h + s * 32 + lane);
        acc.x = acc.x * scale + p * h4.x;
        acc.y = acc.y * scale + p * h4.y;
        acc.z = acc.z * scale + p * h4.z;
        acc.w = acc.w * scale + p * h4.w;
    }
    float  inv = 1.0f / (ssum + 1e-16f);
    float4 b4  = ((const float4*)bias)[lane];
    float4 r;
    r.x = gelu_exact(acc.x * inv + b4.x);
    r.y = gelu_exact(acc.y * inv + b4.y);
    r.z = gelu_exact(acc.z * inv + b4.z);
    r.w = gelu_exact(acc.w * inv + b4.w);
    ((float4*)out)[dst * 32 + lane] = r;
}

extern "C" void kernel_launch(void* const* d_in, const int* in_sizes, int n_in,
                              void* d_out, int out_size) {
    const int*   label = (const int*)d_in[0];
    const int*   ei    = (const int*)d_in[1];
    // d_in[2] = weight (unused by GATConv)
    const float* rq    = (const float*)d_in[3];
    const float* emb   = (const float*)d_in[4];
    const float* rw    = (const float*)d_in[5];
    const float* rb    = (const float*)d_in[6];
    const float* W0    = (const float*)d_in[7];
    const float* as0   = (const float*)d_in[8];
    const float* ad0   = (const float*)d_in[9];
    const float* b0    = (const float*)d_in[10];
    const float* W1    = (const float*)d_in[11];
    const float* as1   = (const float*)d_in[12];
    const float* ad1   = (const float*)d_in[13];
    const float* b1    = (const float*)d_in[14];
    const float* W2    = (const float*)d_in[15];
    const float* as2   = (const float*)d_in[16];
    const float* ad2   = (const float*)d_in[17];
    const float* b2    = (const float*)d_in[18];
    float* out = (float*)d_out;

    float* g_x_p;   cudaGetSymbolAddress((void**)&g_x_p, g_x);
    float* g_h_p;   cudaGetSymbolAddress((void**)&g_h_p, g_h);

    // preprocessing
    k_init<<<(NN + 255) / 256, 256>>>();
    k_rq<<<256, 256>>>(rq);
    k_hist<<<(NE + 255) / 256, 256>>>(ei);
    k_scan1<<<NBLK, SCAN_B>>>();
    k_scan2<<<1, 64>>>();
    k_scan3<<<(NN + 255) / 256, 256>>>();
    k_scatter<<<(TOTE + 255) / 256, 256>>>(ei);
    k_x0<<<(NN * EMBD + 255) / 256, 256>>>(label, rq, emb, rw, rb);

    const int gemm_blocks = (NN + 63) / 64;
    const int warp_blocks = (NN + 7) / 8;   // 8 warps per 256-thread block

    // layer 0
    k_gemm<<<gemm_blocks, 256>>>(g_x_p, W0, g_h_p, as0, ad0);
    k_agg<<<warp_blocks, 256>>>(b0, g_x_p);
    // layer 1
    k_gemm<<<gemm_blocks, 256>>>(g_x_p, W1, g_h_p, as1, ad1);
    k_agg<<<warp_blocks, 256>>>(b1, g_x_p);
    // layer 2
    k_gemm<<<gemm_blocks, 256>>>(g_x_p, W2, g_h_p, as2, ad2);
    k_agg<<<warp_blocks, 256>>>(b2, out);
}

// round 3
// speedup vs baseline: 1.2056x; 1.0223x over previous
#include <cuda_runtime.h>
#include <math.h>

#define NN   50000
#define NE   800000
#define TOTE (NE + NN)
#define HC   128
#define NH   4
#define EMBD 64
#define SCAN_B 1024
#define NBLK  ((NN + SCAN_B - 1) / SCAN_B)   // 49

typedef unsigned long long ull;

// ---- scratch (device globals; no allocation allowed) ----
__device__ float  g_x[NN * HC];
__device__ float  g_h[NN * HC];
__device__ float  g_als[NN * NH];
__device__ float  g_ald[NN * NH];
__device__ int    g_srcs[TOTE];
__device__ int    g_rowptr[NN + 1];
__device__ int    g_cursor[NN];
__device__ int    g_deg[NN];
__device__ int    g_bsum[NBLK];
__device__ int    g_boff[NBLK];
__device__ double g_sum;
__device__ double g_sumsq;

// ---- f32x2 packed-FMA helpers (Blackwell FFMA2, PTX-only) ----
__device__ __forceinline__ ull packf2(float lo, float hi) {
    ull d;
    asm("mov.b64 %0, {%1, %2};" : "=l"(d) : "f"(lo), "f"(hi));
    return d;
}
__device__ __forceinline__ void unpackf2(ull v, float& lo, float& hi) {
    asm("mov.b64 {%0, %1}, %2;" : "=f"(lo), "=f"(hi) : "l"(v));
}
__device__ __forceinline__ ull ffma2(ull a, ull b, ull c) {
    ull d;
    asm("fma.rn.f32x2 %0, %1, %2, %3;" : "=l"(d) : "l"(a), "l"(b), "l"(c));
    return d;
}

// ---------------------------------------------------------------------------
__global__ void k_init() {
    int i = blockIdx.x * blockDim.x + threadIdx.x;
    if (i < NN) g_deg[i] = 1;           // self-loop pre-counted
    if (i == 0) { g_sum = 0.0; g_sumsq = 0.0; }
}

__global__ void k_rq(const float* __restrict__ rq) {
    __shared__ double ss[256], ss2[256];
    double s = 0.0, s2 = 0.0;
    for (int i = blockIdx.x * blockDim.x + threadIdx.x; i < NN;
         i += gridDim.x * blockDim.x) {
        double v = (double)rq[i];
        s += v; s2 += v * v;
    }
    ss[threadIdx.x] = s; ss2[threadIdx.x] = s2;
    __syncthreads();
    for (int o = 128; o; o >>= 1) {
        if (threadIdx.x < o) {
            ss[threadIdx.x]  += ss[threadIdx.x + o];
            ss2[threadIdx.x] += ss2[threadIdx.x + o];
        }
        __syncthreads();
    }
    if (threadIdx.x == 0) {
        atomicAdd(&g_sum,  ss[0]);
        atomicAdd(&g_sumsq, ss2[0]);
    }
}

__global__ void k_hist(const int* __restrict__ ei) {
    int e = blockIdx.x * blockDim.x + threadIdx.x;
    if (e < NE) atomicAdd(&g_deg[__ldg(ei + NE + e)], 1);
}

// ---- parallel 3-phase exclusive scan over g_deg ----
__global__ void k_scan1() {
    __shared__ int sd[SCAN_B];
    int t = threadIdx.x;
    int gi = blockIdx.x * SCAN_B + t;
    int v = (gi < NN) ? g_deg[gi] : 0;
    sd[t] = v;
    __syncthreads();
#pragma unroll
    for (int off = 1; off < SCAN_B; off <<= 1) {
        int x = (t >= off) ? sd[t - off] : 0;
        __syncthreads();
        sd[t] += x;
        __syncthreads();
    }
    if (gi < NN) g_rowptr[gi] = sd[t] - v;          // exclusive within block
    if (t == SCAN_B - 1) g_bsum[blockIdx.x] = sd[t];
}

__global__ void k_scan2() {                          // 1 block, 64 threads
    __shared__ int sd[64];
    int t = threadIdx.x;
    int v = (t < NBLK) ? g_bsum[t] : 0;
    sd[t] = v;
    __syncthreads();
#pragma unroll
    for (int off = 1; off < 64; off <<= 1) {
        int x = (t >= off) ? sd[t - off] : 0;
        __syncthreads();
        sd[t] += x;
        __syncthreads();
    }
    if (t < NBLK) g_boff[t] = sd[t] - v;             // exclusive
}

__global__ void k_scan3() {
    int i = blockIdx.x * blockDim.x + threadIdx.x;
    if (i < NN) {
        int r = g_rowptr[i] + g_boff[i / SCAN_B];
        g_rowptr[i] = r;
        g_cursor[i] = r;
    }
    if (i == 0) g_rowptr[NN] = TOTE;
}

__global__ void k_scatter(const int* __restrict__ ei) {
    int e = blockIdx.x * blockDim.x + threadIdx.x;
    if (e >= TOTE) return;
    int s, d;
    if (e < NE) { s = __ldg(ei + e); d = __ldg(ei + NE + e); }
    else        { s = e - NE; d = s; }
    int pos = atomicAdd(&g_cursor[d], 1);
    g_srcs[pos] = s;
}

__global__ void k_x0(const int* __restrict__ label, const float* __restrict__ rq,
                     const float* __restrict__ emb, const float* __restrict__ rw,
                     const float* __restrict__ rb) {
    int idx = blockIdx.x * blockDim.x + threadIdx.x;
    if (idx >= NN * EMBD) return;
    int i = idx >> 6, j = idx & 63;
    double mean = g_sum / NN;
    double var  = (g_sumsq - NN * mean * mean) / (NN - 1);
    float  stdv = (float)sqrt(var);
    float  rqn  = (rq[i] - (float)mean) / (stdv + 1e-6f);
    g_x[i * HC + j]        = emb[label[i] * EMBD + j];
    g_x[i * HC + EMBD + j] = rqn * rw[j] + rb[j];
}

// ---------------------------------------------------------------------------
// GEMM: O[n,128] = X[n,128] @ W[128,128], fp32 via packed f32x2 FMA.
// 128-row block tile, K-tile 32, 8 warps. Thread = 16 rows (8 row-pairs) x 4 cols.
// x-tile stored K-major transposed so row-pairs load directly as LDS.64.
__global__ __launch_bounds__(256) void k_gemm(const float* __restrict__ X,
                                              const float* __restrict__ W,
                                              float* __restrict__ O,
                                              const float* __restrict__ asrc,
                                              const float* __restrict__ adst) {
    __shared__ float xs[32][130];     // [k][row], pad keeps 8B align + low conflicts
    __shared__ float ws[32][HC];
    int tid = threadIdx.x;
    int ty  = tid >> 5, tx = tid & 31;
    int row0 = blockIdx.x * 128;

    ull acc2[8][4];                   // [row-pair][channel] = {row2j, row2j+1}
#pragma unroll
    for (int j = 0; j < 8; j++)
#pragma unroll
        for (int c = 0; c < 4; c++) acc2[j][c] = 0ull;

    for (int kb = 0; kb < HC; kb += 32) {
#pragma unroll
        for (int j = 0; j < 4; j++) {        // 128 rows x 32 k, float4 loads
            int idx = j * 256 + tid;         // 0..1023
            int row = idx >> 3, kq = idx & 7;
            float4 v = make_float4(0.f, 0.f, 0.f, 0.f);
            int gr = row0 + row;
            if (gr < NN) v = *(const float4*)&X[gr * HC + kb + kq * 4];
            xs[kq * 4 + 0][row] = v.x;
            xs[kq * 4 + 1][row] = v.y;
            xs[kq * 4 + 2][row] = v.z;
            xs[kq * 4 + 3][row] = v.w;
        }
#pragma unroll
        for (int j = 0; j < 16; j++) {       // 32x128 w-tile
            int idx = j * 256 + tid;
            int k = idx >> 7, c = idx & 127;
            ws[k][c] = W[(kb + k) * HC + c];
        }
        __syncthreads();
#pragma unroll
        for (int k = 0; k < 32; k++) {
            float4 b4 = *(const float4*)&ws[k][tx * 4];
            ull bx = packf2(b4.x, b4.x);
            ull by = packf2(b4.y, b4.y);
            ull bz = packf2(b4.z, b4.z);
            ull bw = packf2(b4.w, b4.w);
#pragma unroll
            for (int j = 0; j < 8; j++) {
                ull a2 = *(const ull*)&xs[k][ty * 16 + 2 * j];  // broadcast LDS.64
                acc2[j][0] = ffma2(a2, bx, acc2[j][0]);
                acc2[j][1] = ffma2(a2, by, acc2[j][1]);
                acc2[j][2] = ffma2(a2, bz, acc2[j][2]);
                acc2[j][3] = ffma2(a2, bw, acc2[j][3]);
            }
        }
        __syncthreads();
    }

    float4 as4 = ((const float4*)asrc)[tx];
    float4 ad4 = ((const float4*)adst)[tx];
    int head = tx >> 3;
#pragma unroll
    for (int j = 0; j < 8; j++) {
        float lo[4], hi[4];
#pragma unroll
        for (int c = 0; c < 4; c++) unpackf2(acc2[j][c], lo[c], hi[c]);
#pragma unroll
        for (int half = 0; half < 2; half++) {
            int row = row0 + ty * 16 + 2 * j + half;
            if (row < NN) {
                float4 v = half ? make_float4(hi[0], hi[1], hi[2], hi[3])
                                : make_float4(lo[0], lo[1], lo[2], lo[3]);
                ((float4*)O)[row * 32 + tx] = v;
                float s = v.x * as4.x + v.y * as4.y + v.z * as4.z + v.w * as4.w;
                float d = v.x * ad4.x + v.y * ad4.y + v.z * ad4.z + v.w * ad4.w;
#pragma unroll
                for (int off = 4; off; off >>= 1) {
                    s += __shfl_down_sync(0xffffffffu, s, off, 8);
                    d += __shfl_down_sync(0xffffffffu, d, off, 8);
                }
                if ((tx & 7) == 0) {
                    g_als[row * NH + head] = s;
                    g_ald[row * NH + head] = d;
                }
            }
        }
    }
}

__device__ __forceinline__ float gelu_exact(float x) {
    return 0.5f * x * (1.0f + erff(x * 0.70710678118654752f));
}
__device__ __forceinline__ float lrelu(float v) {
    return v > 0.0f ? v : 0.2f * v;
}

// one warp per destination node: online softmax + weighted sum, 4-edge MLP unroll
__global__ void k_agg(const float* __restrict__ bias, float* __restrict__ out) {
    int dst  = blockIdx.x * (blockDim.x >> 5) + (threadIdx.x >> 5);
    int lane = threadIdx.x & 31;
    if (dst >= NN) return;
    int beg = g_rowptr[dst], end = g_rowptr[dst + 1];
    int head = lane >> 3;
    float ald = g_ald[dst * NH + head];

    float  m    = -1e30f;
    float  ssum = 0.0f;
    float4 acc  = make_float4(0.f, 0.f, 0.f, 0.f);

    int e  = beg;
    int n4 = beg + ((end - beg) & ~3);
    for (; e < n4; e += 4) {
        int s0 = __ldg(g_srcs + e);
        int s1 = __ldg(g_srcs + e + 1);
        int s2 = __ldg(g_srcs + e + 2);
        int s3 = __ldg(g_srcs + e + 3);
        float v0 = lrelu(__ldg(g_als + s0 * NH + head) + ald);
        float v1 = lrelu(__ldg(g_als + s1 * NH + head) + ald);
        float v2 = lrelu(__ldg(g_als + s2 * NH + head) + ald);
        float v3 = lrelu(__ldg(g_als + s3 * NH + head) + ald);
        float4 h0 = __ldg((const float4*)g_h + s0 * 32 + lane);
        float4 h1 = __ldg((const float4*)g_h + s1 * 32 + lane);
        float4 h2 = __ldg((const float4*)g_h + s2 * 32 + lane);
        float4 h3 = __ldg((const float4*)g_h + s3 * 32 + lane);
        float mnew = fmaxf(m, fmaxf(fmaxf(v0, v1), fmaxf(v2, v3)));
        float scale = __expf(m - mnew);
        float p0 = __expf(v0 - mnew);
        float p1 = __expf(v1 - mnew);
        float p2 = __expf(v2 - mnew);
        float p3 = __expf(v3 - mnew);
        m = mnew;
        ssum = ssum * scale + ((p0 + p1) + (p2 + p3));
        acc.x = ((acc.x * scale + p0 * h0.x) + p1 * h1.x) + (p2 * h2.x + p3 * h3.x);
        acc.y = ((acc.y * scale + p0 * h0.y) + p1 * h1.y) + (p2 * h2.y + p3 * h3.y);
        acc.z = ((acc.z * scale + p0 * h0.z) + p1 * h1.z) + (p2 * h2.z + p3 * h3.z);
        acc.w = ((acc.w * scale + p0 * h0.w) + p1 * h1.w) + (p2 * h2.w + p3 * h3.w);
    }
    for (; e < end; e++) {
        int s = __ldg(g_srcs + e);
        float v = lrelu(__ldg(g_als + s * NH + head) + ald);
        float mnew  = fmaxf(m, v);
        float scale = __expf(m - mnew);
        float p     = __expf(v - mnew);
        m = mnew;
        ssum = ssum * scale + p;
        float4 h4 = __ldg((const float4*)g_h + s * 32 + lane);
        acc.x = acc.x * scale + p * h4.x;
        acc.y = acc.y * scale + p * h4.y;
        acc.z = acc.z * scale + p * h4.z;
        acc.w = acc.w * scale + p * h4.w;
    }
    float  inv = 1.0f / (ssum + 1e-16f);
    float4 b4  = ((const float4*)bias)[lane];
    float4 r;
    r.x = gelu_exact(acc.x * inv + b4.x);
    r.y = gelu_exact(acc.y * inv + b4.y);
    r.z = gelu_exact(acc.z * inv + b4.z);
    r.w = gelu_exact(acc.w * inv + b4.w);
    ((float4*)out)[dst * 32 + lane] = r;
}

extern "C" void kernel_launch(void* const* d_in, const int* in_sizes, int n_in,
                              void* d_out, int out_size) {
    const int*   label = (const int*)d_in[0];
    const int*   ei    = (const int*)d_in[1];
    // d_in[2] = weight (unused by GATConv)
    const float* rq    = (const float*)d_in[3];
    const float* emb   = (const float*)d_in[4];
    const float* rw    = (const float*)d_in[5];
    const float* rb    = (const float*)d_in[6];
    const float* W0    = (const float*)d_in[7];
    const float* as0   = (const float*)d_in[8];
    const float* ad0   = (const float*)d_in[9];
    const float* b0    = (const float*)d_in[10];
    const float* W1    = (const float*)d_in[11];
    const float* as1   = (const float*)d_in[12];
    const float* ad1   = (const float*)d_in[13];
    const float* b1    = (const float*)d_in[14];
    const float* W2    = (const float*)d_in[15];
    const float* as2   = (const float*)d_in[16];
    const float* ad2   = (const float*)d_in[17];
    const float* b2    = (const float*)d_in[18];
    float* out = (float*)d_out;

    float* g_x_p;   cudaGetSymbolAddress((void**)&g_x_p, g_x);
    float* g_h_p;   cudaGetSymbolAddress((void**)&g_h_p, g_h);

    // preprocessing
    k_init<<<(NN + 255) / 256, 256>>>();
    k_rq<<<256, 256>>>(rq);
    k_hist<<<(NE + 255) / 256, 256>>>(ei);
    k_scan1<<<NBLK, SCAN_B>>>();
    k_scan2<<<1, 64>>>();
    k_scan3<<<(NN + 255) / 256, 256>>>();
    k_scatter<<<(TOTE + 255) / 256, 256>>>(ei);
    k_x0<<<(NN * EMBD + 255) / 256, 256>>>(label, rq, emb, rw, rb);

    const int gemm_blocks = (NN + 127) / 128;
    const int warp_blocks = (NN + 7) / 8;   // 8 warps per 256-thread block

    // layer 0
    k_gemm<<<gemm_blocks, 256>>>(g_x_p, W0, g_h_p, as0, ad0);
    k_agg<<<warp_blocks, 256>>>(b0, g_x_p);
    // layer 1
    k_gemm<<<gemm_blocks, 256>>>(g_x_p, W1, g_h_p, as1, ad1);
    k_agg<<<warp_blocks, 256>>>(b1, g_x_p);
    // layer 2
    k_gemm<<<gemm_blocks, 256>>>(g_x_p, W2, g_h_p, as2, ad2);
    k_agg<<<warp_blocks, 256>>>(b2, out);
}